// round 2
// baseline (speedup 1.0000x reference)
#include <cuda_runtime.h>
#include <math.h>
#include <stdio.h>

#define BSZ 1000
#define TSZ 100
#define ISZ 264
#define HSZ 100
#define G4  400   // 4*H

// ---------------- device scratch (static: no allocation allowed) ----------
__device__ float g_X[(size_t)BSZ * TSZ * G4];     // encoder gate inputs, 160MB
__device__ float g_henc[BSZ * HSZ];
__device__ float g_cenc[BSZ * HSZ];
__device__ float g_G0[BSZ * G4];                  // decoder step-0 gates
__device__ float g_Weff[G4 * HSZ];                // folded decoder recurrence weight
__device__ float g_beff[G4];                      // folded decoder bias
__device__ float g_hdec[(size_t)BSZ * TSZ * HSZ]; // decoder hidden states, 40MB
__device__ float g_loss[2];                       // [0]=reconstruct sum, [1]=predict sum

// ---------------- small kernels -------------------------------------------
__global__ void zero_loss_kernel(float* loss) { loss[0] = 0.f; loss[1] = 0.f; }

__global__ void finalize_kernel(const float* loss, float* out, float inv) {
    out[0] = loss[0] * inv;   // reconstruct_loss
    out[1] = loss[1] * inv;   // predict_loss
}

// Weff[j][k] = Whh[j][k] + sum_i Wih[j][i]*fcW[i][k]
// beff[j]    = bih[j] + bhh[j] + sum_i Wih[j][i]*fcb[i]
__global__ __launch_bounds__(128) void fold_kernel(
    const float* __restrict__ Wih, const float* __restrict__ Whh,
    const float* __restrict__ fcW, const float* __restrict__ fcb,
    const float* __restrict__ bih, const float* __restrict__ bhh,
    float* __restrict__ Weff, float* __restrict__ beff)
{
    int j = blockIdx.x;          // 0..399
    int tid = threadIdx.x;       // 128
    __shared__ float swih[ISZ];
    __shared__ float red[128];
    for (int i = tid; i < ISZ; i += 128) swih[i] = Wih[j * ISZ + i];
    __syncthreads();
    if (tid < HSZ) {
        float acc = Whh[j * HSZ + tid];
        #pragma unroll 4
        for (int i = 0; i < ISZ; ++i)
            acc = fmaf(swih[i], fcW[i * HSZ + tid], acc);
        Weff[j * HSZ + tid] = acc;
    }
    float p = 0.f;
    for (int i = tid; i < ISZ; i += 128) p = fmaf(swih[i], fcb[i], p);
    red[tid] = p;
    __syncthreads();
    for (int s = 64; s > 0; s >>= 1) {
        if (tid < s) red[tid] += red[tid + s];
        __syncthreads();
    }
    if (tid == 0) beff[j] = bih[j] + bhh[j] + red[0];
}

// ---------------- generic NT GEMM: C = A*B^T (+bias), optional MSE epilogue
// A: [M,K] row-major, B: [N,K] row-major.
// If lossOut != null: accumulate sum((C - ref)^2) into *lossOut (C not stored).
// revT > 0 means ref row index is time-reversed within blocks of revT rows.
__global__ __launch_bounds__(256) void gemm_nt(
    const float* __restrict__ A, const float* __restrict__ B,
    const float* __restrict__ bias1, const float* __restrict__ bias2,
    float* __restrict__ C, int M, int N, int K,
    const float* __restrict__ ref, float* __restrict__ lossOut, int revT)
{
    const int BK = 16, LDSR = 68;
    __shared__ float As[BK * LDSR];
    __shared__ float Bs[BK * LDSR];
    __shared__ float red[256];
    int tid = threadIdx.x;
    int tx = tid & 15, ty = tid >> 4;
    int m0 = blockIdx.y * 64, n0 = blockIdx.x * 64;
    float acc[4][4];
    #pragma unroll
    for (int i = 0; i < 4; ++i)
        #pragma unroll
        for (int j = 0; j < 4; ++j) acc[i][j] = 0.f;

    for (int k0 = 0; k0 < K; k0 += BK) {
        #pragma unroll
        for (int l = 0; l < 4; ++l) {
            int i = tid + l * 256;
            int r = i >> 4, c = i & 15;
            int m = m0 + r, k = k0 + c;
            As[c * LDSR + r] = (m < M && k < K) ? A[(size_t)m * K + k] : 0.f;
        }
        #pragma unroll
        for (int l = 0; l < 4; ++l) {
            int i = tid + l * 256;
            int r = i >> 4, c = i & 15;
            int n = n0 + r, k = k0 + c;
            Bs[c * LDSR + r] = (n < N && k < K) ? B[(size_t)n * K + k] : 0.f;
        }
        __syncthreads();
        #pragma unroll
        for (int kk = 0; kk < BK; ++kk) {
            float4 a4 = *(const float4*)(As + kk * LDSR + ty * 4);
            float4 b4 = *(const float4*)(Bs + kk * LDSR + tx * 4);
            float av[4] = {a4.x, a4.y, a4.z, a4.w};
            float bv[4] = {b4.x, b4.y, b4.z, b4.w};
            #pragma unroll
            for (int i = 0; i < 4; ++i)
                #pragma unroll
                for (int j = 0; j < 4; ++j)
                    acc[i][j] = fmaf(av[i], bv[j], acc[i][j]);
        }
        __syncthreads();
    }

    float bv[4];
    #pragma unroll
    for (int j = 0; j < 4; ++j) {
        int n = n0 + tx * 4 + j;
        float v = 0.f;
        if (n < N) {
            if (bias1) v += bias1[n];
            if (bias2) v += bias2[n];
        }
        bv[j] = v;
    }

    if (!lossOut) {
        #pragma unroll
        for (int i = 0; i < 4; ++i) {
            int m = m0 + ty * 4 + i;
            if (m < M) {
                #pragma unroll
                for (int j = 0; j < 4; ++j) {
                    int n = n0 + tx * 4 + j;
                    if (n < N) C[(size_t)m * N + n] = acc[i][j] + bv[j];
                }
            }
        }
    } else {
        float ls = 0.f;
        #pragma unroll
        for (int i = 0; i < 4; ++i) {
            int m = m0 + ty * 4 + i;
            if (m < M) {
                const float* rrow;
                if (revT > 0) {
                    int b = m / revT, t = m - b * revT;
                    rrow = ref + ((size_t)b * revT + (revT - 1 - t)) * N;
                } else {
                    rrow = ref + (size_t)m * N;
                }
                #pragma unroll
                for (int j = 0; j < 4; ++j) {
                    int n = n0 + tx * 4 + j;
                    if (n < N) {
                        float d = acc[i][j] + bv[j] - rrow[n];
                        ls = fmaf(d, d, ls);
                    }
                }
            }
        }
        red[tid] = ls;
        __syncthreads();
        for (int s = 128; s > 0; s >>= 1) {
            if (tid < s) red[tid] += red[tid + s];
            __syncthreads();
        }
        if (tid == 0) atomicAdd(lossOut, red[0]);
    }
}

// ---------------- LSTM recurrence kernels ----------------------------------
// 7 batch elements per CTA, 128 threads, recurrence weight in SMEM.
// Thread tid<100 computes gates j = 4*tid..4*tid+3 for all 7 batches.

__device__ __forceinline__ float sigf(float x) { return 1.f / (1.f + expf(-x)); }

// sW: 40000 | sH: 700 | sC: 700 | sG: 2800  (floats)
#define RNN_SMEM_F   (40000 + 700 + 700 + 2800)
#define DEC_SMEM_F   (RNN_SMEM_F + 400)

__global__ __launch_bounds__(128, 1) void rnn_enc(
    const float* __restrict__ X, const float* __restrict__ Whh,
    float* __restrict__ hf, float* __restrict__ cf)
{
    extern __shared__ float s[];
    float* sW = s;
    float* sH = s + 40000;
    float* sC = s + 40700;
    float* sG = s + 41400;
    int tid = threadIdx.x;
    int b0 = blockIdx.x * 7;
    int nv = BSZ - b0; if (nv > 7) nv = 7;

    for (int i = tid; i < 10000; i += 128)
        ((float4*)sW)[i] = ((const float4*)Whh)[i];
    for (int i = tid; i < 1400; i += 128) sH[i] = 0.f;  // zeros sH and sC
    __syncthreads();

    for (int t = 0; t < TSZ; ++t) {
        if (tid < 100) {
            int j0 = tid * 4;
            // prefetch this step's gate inputs (independent of recurrence)
            float4 xv[7];
            #pragma unroll
            for (int g = 0; g < 7; ++g) {
                xv[g] = make_float4(0.f, 0.f, 0.f, 0.f);
                if (g < nv)
                    xv[g] = *(const float4*)(X + ((size_t)(b0 + g) * TSZ + t) * G4 + j0);
            }
            float acc[7][4];
            #pragma unroll
            for (int g = 0; g < 7; ++g)
                #pragma unroll
                for (int jj = 0; jj < 4; ++jj) acc[g][jj] = 0.f;
            const float4* w0 = (const float4*)(sW + j0 * HSZ);
            #pragma unroll 5
            for (int k4 = 0; k4 < 25; ++k4) {
                float4 w[4];
                w[0] = w0[k4]; w[1] = w0[25 + k4]; w[2] = w0[50 + k4]; w[3] = w0[75 + k4];
                #pragma unroll
                for (int g = 0; g < 7; ++g) {
                    float4 h4 = ((const float4*)(sH + g * HSZ))[k4];
                    #pragma unroll
                    for (int jj = 0; jj < 4; ++jj) {
                        acc[g][jj] = fmaf(h4.x, w[jj].x, acc[g][jj]);
                        acc[g][jj] = fmaf(h4.y, w[jj].y, acc[g][jj]);
                        acc[g][jj] = fmaf(h4.z, w[jj].z, acc[g][jj]);
                        acc[g][jj] = fmaf(h4.w, w[jj].w, acc[g][jj]);
                    }
                }
            }
            #pragma unroll
            for (int g = 0; g < 7; ++g) {
                float4 ov;
                ov.x = acc[g][0] + xv[g].x;
                ov.y = acc[g][1] + xv[g].y;
                ov.z = acc[g][2] + xv[g].z;
                ov.w = acc[g][3] + xv[g].w;
                *(float4*)(sG + g * G4 + j0) = ov;
            }
        }
        __syncthreads();
        for (int idx = tid; idx < 700; idx += 128) {
            int g = idx / 100, k = idx - g * 100;
            const float* gg = sG + g * G4;
            float iv = sigf(gg[k]);
            float fv = sigf(gg[100 + k]);
            float gv = tanhf(gg[200 + k]);
            float ov = sigf(gg[300 + k]);
            float c = fmaf(fv, sC[idx], iv * gv);
            sC[idx] = c;
            sH[idx] = ov * tanhf(c);
        }
        __syncthreads();
    }
    for (int idx = tid; idx < 700; idx += 128) {
        int g = idx / 100, k = idx - g * 100;
        if (g < nv) {
            hf[(b0 + g) * HSZ + k] = sH[idx];
            cf[(b0 + g) * HSZ + k] = sC[idx];
        }
    }
}

__global__ __launch_bounds__(128, 1) void rnn_dec(
    const float* __restrict__ G0, const float* __restrict__ Weff,
    const float* __restrict__ beff,
    const float* __restrict__ h0, const float* __restrict__ c0,
    float* __restrict__ hall)
{
    extern __shared__ float s[];
    float* sW = s;
    float* sH = s + 40000;
    float* sC = s + 40700;
    float* sG = s + 41400;
    float* sB = s + 44200;
    int tid = threadIdx.x;
    int b0 = blockIdx.x * 7;
    int nv = BSZ - b0; if (nv > 7) nv = 7;

    for (int i = tid; i < 10000; i += 128)
        ((float4*)sW)[i] = ((const float4*)Weff)[i];
    for (int i = tid; i < G4; i += 128) sB[i] = beff[i];
    for (int idx = tid; idx < 700; idx += 128) {
        int g = idx / 100, k = idx - g * 100;
        float hv = 0.f, cv = 0.f;
        if (g < nv) {
            hv = h0[(b0 + g) * HSZ + k];
            cv = c0[(b0 + g) * HSZ + k];
        }
        sH[idx] = hv; sC[idx] = cv;
    }
    __syncthreads();

    for (int t = 0; t < TSZ; ++t) {
        if (tid < 100) {
            int j0 = tid * 4;
            if (t == 0) {
                // step 0: gates fully precomputed (G0 = h_enc@Whh^T + bih + bhh)
                #pragma unroll
                for (int g = 0; g < 7; ++g) {
                    float4 xv = make_float4(0.f, 0.f, 0.f, 0.f);
                    if (g < nv)
                        xv = *(const float4*)(G0 + (size_t)(b0 + g) * G4 + j0);
                    *(float4*)(sG + g * G4 + j0) = xv;
                }
            } else {
                float4 bb = *(const float4*)(sB + j0);
                float acc[7][4];
                #pragma unroll
                for (int g = 0; g < 7; ++g)
                    #pragma unroll
                    for (int jj = 0; jj < 4; ++jj) acc[g][jj] = 0.f;
                const float4* w0 = (const float4*)(sW + j0 * HSZ);
                #pragma unroll 5
                for (int k4 = 0; k4 < 25; ++k4) {
                    float4 w[4];
                    w[0] = w0[k4]; w[1] = w0[25 + k4]; w[2] = w0[50 + k4]; w[3] = w0[75 + k4];
                    #pragma unroll
                    for (int g = 0; g < 7; ++g) {
                        float4 h4 = ((const float4*)(sH + g * HSZ))[k4];
                        #pragma unroll
                        for (int jj = 0; jj < 4; ++jj) {
                            acc[g][jj] = fmaf(h4.x, w[jj].x, acc[g][jj]);
                            acc[g][jj] = fmaf(h4.y, w[jj].y, acc[g][jj]);
                            acc[g][jj] = fmaf(h4.z, w[jj].z, acc[g][jj]);
                            acc[g][jj] = fmaf(h4.w, w[jj].w, acc[g][jj]);
                        }
                    }
                }
                #pragma unroll
                for (int g = 0; g < 7; ++g) {
                    float4 ov;
                    ov.x = acc[g][0] + bb.x;
                    ov.y = acc[g][1] + bb.y;
                    ov.z = acc[g][2] + bb.z;
                    ov.w = acc[g][3] + bb.w;
                    *(float4*)(sG + g * G4 + j0) = ov;
                }
            }
        }
        __syncthreads();
        for (int idx = tid; idx < 700; idx += 128) {
            int g = idx / 100, k = idx - g * 100;
            const float* gg = sG + g * G4;
            float iv = sigf(gg[k]);
            float fv = sigf(gg[100 + k]);
            float gv = tanhf(gg[200 + k]);
            float ov = sigf(gg[300 + k]);
            float c = fmaf(fv, sC[idx], iv * gv);
            sC[idx] = c;
            float h = ov * tanhf(c);
            sH[idx] = h;
            if (g < nv)
                hall[((size_t)(b0 + g) * TSZ + t) * HSZ + k] = h;
        }
        __syncthreads();
    }
}

// ---------------- launch ----------------------------------------------------
extern "C" void kernel_launch(void* const* d_in, const int* in_sizes, int n_in,
                              void* d_out, int out_size)
{
    const float* src     = (const float*)d_in[0];
    const float* trg     = (const float*)d_in[1];
    const float* enc_Wih = (const float*)d_in[2];
    const float* enc_Whh = (const float*)d_in[3];
    const float* enc_bih = (const float*)d_in[4];
    const float* enc_bhh = (const float*)d_in[5];
    const float* pd_Wih  = (const float*)d_in[6];
    const float* pd_Whh  = (const float*)d_in[7];
    const float* pd_bih  = (const float*)d_in[8];
    const float* pd_bhh  = (const float*)d_in[9];
    const float* pd_fcW  = (const float*)d_in[10];
    const float* pd_fcb  = (const float*)d_in[11];
    const float* rd_Wih  = (const float*)d_in[12];
    const float* rd_Whh  = (const float*)d_in[13];
    const float* rd_bih  = (const float*)d_in[14];
    const float* rd_bhh  = (const float*)d_in[15];
    const float* rd_fcW  = (const float*)d_in[16];
    const float* rd_fcb  = (const float*)d_in[17];
    float* out = (float*)d_out;

    float *pX, *pHenc, *pCenc, *pG0, *pWeff, *pBeff, *pHdec, *pLoss;
    cudaGetSymbolAddress((void**)&pX,    g_X);
    cudaGetSymbolAddress((void**)&pHenc, g_henc);
    cudaGetSymbolAddress((void**)&pCenc, g_cenc);
    cudaGetSymbolAddress((void**)&pG0,   g_G0);
    cudaGetSymbolAddress((void**)&pWeff, g_Weff);
    cudaGetSymbolAddress((void**)&pBeff, g_beff);
    cudaGetSymbolAddress((void**)&pHdec, g_hdec);
    cudaGetSymbolAddress((void**)&pLoss, g_loss);

    const int SMEM_ENC = RNN_SMEM_F * 4;
    const int SMEM_DEC = DEC_SMEM_F * 4;
    cudaFuncSetAttribute(rnn_enc, cudaFuncAttributeMaxDynamicSharedMemorySize, SMEM_ENC);
    cudaFuncSetAttribute(rnn_dec, cudaFuncAttributeMaxDynamicSharedMemorySize, SMEM_DEC);

    const int RNN_BLOCKS = (BSZ + 6) / 7;  // 143

    zero_loss_kernel<<<1, 1>>>(pLoss);

    // Phase A: X = src @ enc_Wih^T + (enc_bih + enc_bhh)   [100000 x 400]
    {
        dim3 grid((G4 + 63) / 64, (BSZ * TSZ + 63) / 64);
        gemm_nt<<<grid, 256>>>(src, enc_Wih, enc_bih, enc_bhh, pX,
                               BSZ * TSZ, G4, ISZ, nullptr, nullptr, 0);
    }

    // Encoder recurrence
    rnn_enc<<<RNN_BLOCKS, 128, SMEM_ENC>>>(pX, enc_Whh, pHenc, pCenc);

    // ---- predict decoder ----
    fold_kernel<<<G4, 128>>>(pd_Wih, pd_Whh, pd_fcW, pd_fcb, pd_bih, pd_bhh, pWeff, pBeff);
    {
        dim3 grid((G4 + 63) / 64, (BSZ + 63) / 64);
        gemm_nt<<<grid, 256>>>(pHenc, pd_Whh, pd_bih, pd_bhh, pG0,
                               BSZ, G4, HSZ, nullptr, nullptr, 0);
    }
    rnn_dec<<<RNN_BLOCKS, 128, SMEM_DEC>>>(pG0, pWeff, pBeff, pHenc, pCenc, pHdec);
    {
        dim3 grid((ISZ + 63) / 64, (BSZ * TSZ + 63) / 64);
        gemm_nt<<<grid, 256>>>(pHdec, pd_fcW, pd_fcb, nullptr, nullptr,
                               BSZ * TSZ, ISZ, HSZ, trg, pLoss + 1, 0);
    }

    // ---- reconstruct decoder ----
    fold_kernel<<<G4, 128>>>(rd_Wih, rd_Whh, rd_fcW, rd_fcb, rd_bih, rd_bhh, pWeff, pBeff);
    {
        dim3 grid((G4 + 63) / 64, (BSZ + 63) / 64);
        gemm_nt<<<grid, 256>>>(pHenc, rd_Whh, rd_bih, rd_bhh, pG0,
                               BSZ, G4, HSZ, nullptr, nullptr, 0);
    }
    rnn_dec<<<RNN_BLOCKS, 128, SMEM_DEC>>>(pG0, pWeff, pBeff, pHenc, pCenc, pHdec);
    {
        dim3 grid((ISZ + 63) / 64, (BSZ * TSZ + 63) / 64);
        gemm_nt<<<grid, 256>>>(pHdec, rd_fcW, rd_fcb, nullptr, nullptr,
                               BSZ * TSZ, ISZ, HSZ, src, pLoss + 0, TSZ);
    }

    finalize_kernel<<<1, 1>>>(pLoss, out, 1.0f / (float)(BSZ * TSZ * ISZ));
}